// round 1
// baseline (speedup 1.0000x reference)
#include <cuda_runtime.h>
#include <cuda_fp16.h>
#include <cstdint>

// Problem shape (fixed by the dataset): y[8192,4096] = x[8192,4096] @ sign(W[4096,4096])^T + sign(b[4096])
#define TOKENS_ 8192
#define IN_DIM_ 4096
#define OUT_DIM_ 4096

#define BM 128
#define BN 128
#define BK 64
// 8 warps: 2 along M (64 rows each), 4 along N (32 cols each)

// Scratch (allocation-free rule: __device__ globals)
__device__ __half g_xh[(size_t)TOKENS_ * IN_DIM_];   // x in fp16, [M][K] row-major
__device__ __half g_wh[(size_t)OUT_DIM_ * IN_DIM_];  // sign(W) in fp16, [N][K] row-major

// ---------------------------------------------------------------------------
// Conversion kernels
// ---------------------------------------------------------------------------
__global__ void conv_x_kernel(const float4* __restrict__ x, __half2* __restrict__ xh, int n4) {
    int i = blockIdx.x * blockDim.x + threadIdx.x;
    if (i < n4) {
        float4 v = x[i];
        xh[2 * i + 0] = __floats2half2_rn(v.x, v.y);
        xh[2 * i + 1] = __floats2half2_rn(v.z, v.w);
    }
}

__global__ void conv_w_kernel(const float4* __restrict__ w, __half2* __restrict__ wh, int n4) {
    int i = blockIdx.x * blockDim.x + threadIdx.x;
    if (i < n4) {
        float4 v = w[i];
        const __half p = __float2half_rn(1.0f);
        const __half m = __float2half_rn(-1.0f);
        wh[2 * i + 0] = __halves2half2(v.x >= 0.0f ? p : m, v.y >= 0.0f ? p : m);
        wh[2 * i + 1] = __halves2half2(v.z >= 0.0f ? p : m, v.w >= 0.0f ? p : m);
    }
}

// ---------------------------------------------------------------------------
// GEMM: C[M,N] = A[M,K] * B[N,K]^T + sign(bias), fp16 in, fp32 accum/out
// ---------------------------------------------------------------------------
__device__ __forceinline__ uint32_t sw128(uint32_t byte_off) {
    // SW128 swizzle: xor 16B-chunk bits[6:4] with row%8 bits[9:7] (rows are 128B)
    return byte_off ^ ((byte_off >> 3) & 0x70);
}

__global__ __launch_bounds__(256, 1)
void bingemm_kernel(const __half* __restrict__ A, const __half* __restrict__ B,
                    const float* __restrict__ bias, float* __restrict__ C) {
    extern __shared__ __half smem[];
    // layout: As double-buffered [2][128][64], then Bs [2][128][64]
    __half* As = smem;
    __half* Bs = smem + 2 * BM * BK;

    const int tid  = threadIdx.x;
    const int lane = tid & 31;
    const int warp = tid >> 5;
    const int wm   = warp & 1;   // 0..1  -> 64-row slice
    const int wn   = warp >> 1;  // 0..3  -> 32-col slice
    const int bm   = blockIdx.y;
    const int bn   = blockIdx.x;

    const uint32_t as_base = (uint32_t)__cvta_generic_to_shared(As);
    const uint32_t bs_base = (uint32_t)__cvta_generic_to_shared(Bs);

    const __half* Ag = A + (size_t)(bm * BM) * IN_DIM_;
    const __half* Bg = B + (size_t)(bn * BN) * IN_DIM_;

    float acc[4][4][4];
#pragma unroll
    for (int i = 0; i < 4; i++)
#pragma unroll
        for (int j = 0; j < 4; j++)
#pragma unroll
            for (int k = 0; k < 4; k++) acc[i][j][k] = 0.0f;

    // per-thread ldmatrix address components
    // A (x4): m_off = ((lane>>3)&1)*8 + (lane&7), k_off = ((lane>>4)&1)*8
    const int a_m_off = ((lane >> 3) & 1) * 8 + (lane & 7);
    const int a_k_off = ((lane >> 4) & 1) * 8;
    // B (x2): n_off = lane&7, k_off = ((lane>>3)&1)*8  (lanes 16-31 unused but valid)
    const int b_n_off = lane & 7;
    const int b_k_off = ((lane >> 3) & 1) * 8;

    // tile loader: 128x64 fp16 = 1024 16B chunks per operand, 256 threads -> 4 each
    auto issue = [&](int buf, int kt) {
        const int k0 = kt * BK;
#pragma unroll
        for (int j = 0; j < 4; j++) {
            int idx = tid + j * 256;
            int row = idx >> 3;
            int ch  = idx & 7;
            uint32_t soff = sw128((uint32_t)(row * 128 + ch * 16));
            uint32_t sa = as_base + buf * 16384 + soff;
            const void* ga = (const void*)(Ag + (size_t)row * IN_DIM_ + k0 + ch * 8);
            asm volatile("cp.async.cg.shared.global [%0], [%1], 16;\n" :: "r"(sa), "l"(ga));
            uint32_t sb = bs_base + buf * 16384 + soff;
            const void* gb = (const void*)(Bg + (size_t)row * IN_DIM_ + k0 + ch * 8);
            asm volatile("cp.async.cg.shared.global [%0], [%1], 16;\n" :: "r"(sb), "l"(gb));
        }
        asm volatile("cp.async.commit_group;\n");
    };

    auto compute = [&](int buf) {
        const uint32_t abase = as_base + buf * 16384;
        const uint32_t bbase = bs_base + buf * 16384;
#pragma unroll
        for (int kk = 0; kk < BK; kk += 16) {
            uint32_t a[4][4];
            uint32_t b[4][2];
#pragma unroll
            for (int mi = 0; mi < 4; mi++) {
                int row = wm * 64 + mi * 16 + a_m_off;
                uint32_t addr = abase + sw128((uint32_t)(row * 128 + (kk + a_k_off) * 2));
                asm volatile("ldmatrix.sync.aligned.m8n8.x4.shared.b16 {%0,%1,%2,%3}, [%4];"
                             : "=r"(a[mi][0]), "=r"(a[mi][1]), "=r"(a[mi][2]), "=r"(a[mi][3])
                             : "r"(addr));
            }
#pragma unroll
            for (int ni = 0; ni < 4; ni++) {
                int row = wn * 32 + ni * 8 + b_n_off;
                uint32_t addr = bbase + sw128((uint32_t)(row * 128 + (kk + b_k_off) * 2));
                asm volatile("ldmatrix.sync.aligned.m8n8.x2.shared.b16 {%0,%1}, [%2];"
                             : "=r"(b[ni][0]), "=r"(b[ni][1])
                             : "r"(addr));
            }
#pragma unroll
            for (int mi = 0; mi < 4; mi++) {
#pragma unroll
                for (int ni = 0; ni < 4; ni++) {
                    asm volatile(
                        "mma.sync.aligned.m16n8k16.row.col.f32.f16.f16.f32 "
                        "{%0,%1,%2,%3}, {%4,%5,%6,%7}, {%8,%9}, {%0,%1,%2,%3};"
                        : "+f"(acc[mi][ni][0]), "+f"(acc[mi][ni][1]),
                          "+f"(acc[mi][ni][2]), "+f"(acc[mi][ni][3])
                        : "r"(a[mi][0]), "r"(a[mi][1]), "r"(a[mi][2]), "r"(a[mi][3]),
                          "r"(b[ni][0]), "r"(b[ni][1]));
                }
            }
        }
    };

    const int KT = IN_DIM_ / BK;  // 64
    issue(0, 0);
    for (int kt = 0; kt < KT; ++kt) {
        if (kt + 1 < KT) {
            issue((kt + 1) & 1, kt + 1);
            asm volatile("cp.async.wait_group 1;\n");
        } else {
            asm volatile("cp.async.wait_group 0;\n");
        }
        __syncthreads();
        compute(kt & 1);
        __syncthreads();
    }

    // epilogue: C[t][o] = acc + sign(bias[o])
    const int row_base = bm * BM + wm * 64 + (lane >> 2);
    const int col_base = bn * BN + wn * 32 + (lane & 3) * 2;
#pragma unroll
    for (int ni = 0; ni < 4; ni++) {
        int col = col_base + ni * 8;
        float sb0 = bias[col + 0] >= 0.0f ? 1.0f : -1.0f;
        float sb1 = bias[col + 1] >= 0.0f ? 1.0f : -1.0f;
#pragma unroll
        for (int mi = 0; mi < 4; mi++) {
            int r0 = row_base + mi * 16;
            int r1 = r0 + 8;
            float2 v0 = make_float2(acc[mi][ni][0] + sb0, acc[mi][ni][1] + sb1);
            float2 v1 = make_float2(acc[mi][ni][2] + sb0, acc[mi][ni][3] + sb1);
            *(float2*)(C + (size_t)r0 * OUT_DIM_ + col) = v0;
            *(float2*)(C + (size_t)r1 * OUT_DIM_ + col) = v1;
        }
    }
}

// ---------------------------------------------------------------------------
// Launch
// ---------------------------------------------------------------------------
extern "C" void kernel_launch(void* const* d_in, const int* in_sizes, int n_in,
                              void* d_out, int out_size) {
    const float* x    = (const float*)d_in[0];  // [8192, 4096]
    const float* w    = (const float*)d_in[1];  // [4096, 4096]
    const float* bias = (const float*)d_in[2];  // [4096]
    float* out        = (float*)d_out;          // [8192, 4096]

    void* xh_ptr = nullptr;
    void* wh_ptr = nullptr;
    cudaGetSymbolAddress(&xh_ptr, g_xh);
    cudaGetSymbolAddress(&wh_ptr, g_wh);
    __half* xh = (__half*)xh_ptr;
    __half* wh = (__half*)wh_ptr;

    // conversions
    {
        int n4 = (TOKENS_ * IN_DIM_) / 4;
        conv_x_kernel<<<(n4 + 255) / 256, 256>>>((const float4*)x, (__half2*)xh, n4);
    }
    {
        int n4 = (OUT_DIM_ * IN_DIM_) / 4;
        conv_w_kernel<<<(n4 + 255) / 256, 256>>>((const float4*)w, (__half2*)wh, n4);
    }

    // GEMM
    static bool attr_set = false;
    const int smem_bytes = 2 * (BM * BK + BN * BK) * (int)sizeof(__half);  // 65536
    if (!attr_set) {
        cudaFuncSetAttribute(bingemm_kernel, cudaFuncAttributeMaxDynamicSharedMemorySize,
                             smem_bytes);
        attr_set = true;
    }
    dim3 grid(OUT_DIM_ / BN, TOKENS_ / BM);  // (32, 64)
    bingemm_kernel<<<grid, 256, smem_bytes>>>(xh, wh, bias, out);
}

// round 17
// speedup vs baseline: 1.1418x; 1.1418x over previous
#include <cuda_runtime.h>
#include <cuda_fp16.h>
#include <cstdint>

// y[8192,4096] = x[8192,4096] @ sign(W[4096,4096])^T + sign(b[4096])
#define TOKENS_ 8192
#define IN_DIM_ 4096
#define OUT_DIM_ 4096

#define BM 128
#define BN 256
#define BK 64                    // 64 fp16 = 128B = one SW128 row
#define STAGES 3
#define K_ITERS (IN_DIM_ / BK)   // 64

#define A_STAGE_BYTES (BM * BK * 2)              // 16384
#define B_STAGE_BYTES (BN * BK * 2)              // 32768
#define STAGE_BYTES (A_STAGE_BYTES + B_STAGE_BYTES)  // 49152
#define SMEM_TOTAL (STAGES * STAGE_BYTES)        // 147456

// Scratch (allocation-free rule: __device__ globals)
__device__ __align__(1024) __half g_xh[(size_t)TOKENS_ * IN_DIM_];   // x fp16 [M][K]
__device__ __align__(1024) __half g_wh[(size_t)OUT_DIM_ * IN_DIM_];  // sign(W) fp16 [N][K]

// ---------------------------------------------------------------------------
// Conversion kernels
// ---------------------------------------------------------------------------
__global__ void conv_x_kernel(const float4* __restrict__ x, __half2* __restrict__ xh, int n4) {
    int i = blockIdx.x * blockDim.x + threadIdx.x;
    if (i < n4) {
        float4 v = x[i];
        xh[2 * i + 0] = __floats2half2_rn(v.x, v.y);
        xh[2 * i + 1] = __floats2half2_rn(v.z, v.w);
    }
}

__global__ void conv_w_kernel(const float4* __restrict__ w, __half2* __restrict__ wh, int n4) {
    int i = blockIdx.x * blockDim.x + threadIdx.x;
    if (i < n4) {
        float4 v = w[i];
        const __half p = __float2half_rn(1.0f);
        const __half m = __float2half_rn(-1.0f);
        wh[2 * i + 0] = __halves2half2(v.x >= 0.0f ? p : m, v.y >= 0.0f ? p : m);
        wh[2 * i + 1] = __halves2half2(v.z >= 0.0f ? p : m, v.w >= 0.0f ? p : m);
    }
}

// ---------------------------------------------------------------------------
// GEMM
// ---------------------------------------------------------------------------
__device__ __forceinline__ uint32_t sw128(uint32_t byte_off) {
    return byte_off ^ ((byte_off >> 3) & 0x70);
}

__global__ __launch_bounds__(256, 1)
void bingemm_kernel(const __half* __restrict__ A, const __half* __restrict__ B,
                    const float* __restrict__ bias, float* __restrict__ C) {
    extern __shared__ char smem[];
    const uint32_t sbase = (uint32_t)__cvta_generic_to_shared(smem);

    const int tid  = threadIdx.x;
    const int lane = tid & 31;
    const int warp = tid >> 5;
    const int wm   = warp & 1;   // 2 slices of 64 rows
    const int wn   = warp >> 1;  // 4 slices of 64 cols
    const int m0   = blockIdx.y * BM;
    const int n0   = blockIdx.x * BN;

    const __half* Ag = A + (size_t)m0 * IN_DIM_;
    const __half* Bg = B + (size_t)n0 * IN_DIM_;

    float acc[4][8][4];
#pragma unroll
    for (int i = 0; i < 4; i++)
#pragma unroll
        for (int j = 0; j < 8; j++)
#pragma unroll
            for (int k = 0; k < 4; k++) acc[i][j][k] = 0.0f;

    // ldmatrix lane address components (x4 form)
    // A [m][k]: lanes 0-15 -> rows m0..m15 (two 8-row groups), lanes 16-31 -> k+8 column half
    const int a_m_off = ((lane >> 3) & 1) * 8 + (lane & 7);
    const int a_k_off = ((lane >> 4) & 1) * 8;
    // B [n][k] x4 covering two n8 frags x two k halves:
    const int b_n_off = (lane & 7) + ((lane >> 4) & 1) * 8;
    const int b_k_off = ((lane >> 3) & 1) * 8;

    // ---- cp.async tile loader: A 1024 chunks (4/thread), B 2048 chunks (8/thread)
    auto issue = [&](int slot, int kt) {
        const int k0 = kt * BK;
        const uint32_t st = sbase + slot * STAGE_BYTES;
#pragma unroll
        for (int j = 0; j < 4; j++) {
            int idx = tid + j * 256;
            int row = idx >> 3, ch = idx & 7;
            uint32_t sa = st + sw128((uint32_t)(row * 128 + ch * 16));
            const void* ga = (const void*)(Ag + (size_t)row * IN_DIM_ + k0 + ch * 8);
            asm volatile("cp.async.cg.shared.global [%0], [%1], 16;\n" :: "r"(sa), "l"(ga));
        }
#pragma unroll
        for (int j = 0; j < 8; j++) {
            int idx = tid + j * 256;
            int row = idx >> 3, ch = idx & 7;
            uint32_t sb = st + A_STAGE_BYTES + sw128((uint32_t)(row * 128 + ch * 16));
            const void* gb = (const void*)(Bg + (size_t)row * IN_DIM_ + k0 + ch * 8);
            asm volatile("cp.async.cg.shared.global [%0], [%1], 16;\n" :: "r"(sb), "l"(gb));
        }
        asm volatile("cp.async.commit_group;\n");
    };

    auto compute = [&](int slot) {
        const uint32_t abase = sbase + slot * STAGE_BYTES;
        const uint32_t bbase = abase + A_STAGE_BYTES;
#pragma unroll
        for (int kk = 0; kk < BK; kk += 16) {
            uint32_t a[4][4];
            uint32_t b[8][2];
#pragma unroll
            for (int mi = 0; mi < 4; mi++) {
                int row = wm * 64 + mi * 16 + a_m_off;
                uint32_t addr = abase + sw128((uint32_t)(row * 128 + (kk + a_k_off) * 2));
                asm volatile("ldmatrix.sync.aligned.m8n8.x4.shared.b16 {%0,%1,%2,%3}, [%4];"
                             : "=r"(a[mi][0]), "=r"(a[mi][1]), "=r"(a[mi][2]), "=r"(a[mi][3])
                             : "r"(addr));
            }
#pragma unroll
            for (int np = 0; np < 4; np++) {  // pair of n8 frags per ldmatrix.x4
                int row = wn * 64 + np * 16 + b_n_off;
                uint32_t addr = bbase + sw128((uint32_t)(row * 128 + (kk + b_k_off) * 2));
                asm volatile("ldmatrix.sync.aligned.m8n8.x4.shared.b16 {%0,%1,%2,%3}, [%4];"
                             : "=r"(b[2 * np][0]), "=r"(b[2 * np][1]),
                               "=r"(b[2 * np + 1][0]), "=r"(b[2 * np + 1][1])
                             : "r"(addr));
            }
#pragma unroll
            for (int mi = 0; mi < 4; mi++) {
#pragma unroll
                for (int nj = 0; nj < 8; nj++) {
                    asm volatile(
                        "mma.sync.aligned.m16n8k16.row.col.f32.f16.f16.f32 "
                        "{%0,%1,%2,%3}, {%4,%5,%6,%7}, {%8,%9}, {%0,%1,%2,%3};"
                        : "+f"(acc[mi][nj][0]), "+f"(acc[mi][nj][1]),
                          "+f"(acc[mi][nj][2]), "+f"(acc[mi][nj][3])
                        : "r"(a[mi][0]), "r"(a[mi][1]), "r"(a[mi][2]), "r"(a[mi][3]),
                          "r"(b[nj][0]), "r"(b[nj][1]));
                }
            }
        }
    };

    // prologue: fill STAGES-1 stages
    issue(0, 0);
    issue(1, 1);

    for (int it = 0; it < K_ITERS; ++it) {
        if (it + 2 < K_ITERS)
            asm volatile("cp.async.wait_group 1;\n");
        else
            asm volatile("cp.async.wait_group 0;\n");
        __syncthreads();
        if (it + 2 < K_ITERS) issue((it + 2) % STAGES, it + 2);
        compute(it % STAGES);
    }

    // ---- epilogue: C = acc + sign(bias)
    const int row_base = m0 + wm * 64 + (lane >> 2);
    const int col_base = n0 + wn * 64 + (lane & 3) * 2;
#pragma unroll
    for (int nj = 0; nj < 8; nj++) {
        int col = col_base + nj * 8;
        float sb0 = __ldg(bias + col)     >= 0.0f ? 1.0f : -1.0f;
        float sb1 = __ldg(bias + col + 1) >= 0.0f ? 1.0f : -1.0f;
#pragma unroll
        for (int mi = 0; mi < 4; mi++) {
            int r0 = row_base + mi * 16;
            *(float2*)(C + (size_t)r0 * OUT_DIM_ + col) =
                make_float2(acc[mi][nj][0] + sb0, acc[mi][nj][1] + sb1);
            *(float2*)(C + (size_t)(r0 + 8) * OUT_DIM_ + col) =
                make_float2(acc[mi][nj][2] + sb0, acc[mi][nj][3] + sb1);
        }
    }
}

// ---------------------------------------------------------------------------
// Launch
// ---------------------------------------------------------------------------
extern "C" void kernel_launch(void* const* d_in, const int* in_sizes, int n_in,
                              void* d_out, int out_size) {
    const float* x    = (const float*)d_in[0];  // [8192, 4096]
    const float* w    = (const float*)d_in[1];  // [4096, 4096]
    const float* bias = (const float*)d_in[2];  // [4096]
    float* out        = (float*)d_out;          // [8192, 4096]

    void* xh_ptr = nullptr;
    void* wh_ptr = nullptr;
    cudaGetSymbolAddress(&xh_ptr, g_xh);
    cudaGetSymbolAddress(&wh_ptr, g_wh);
    __half* xh = (__half*)xh_ptr;
    __half* wh = (__half*)wh_ptr;

    {
        int n4 = (TOKENS_ * IN_DIM_) / 4;
        conv_x_kernel<<<(n4 + 255) / 256, 256>>>((const float4*)x, (__half2*)xh, n4);
    }
    {
        int n4 = (OUT_DIM_ * IN_DIM_) / 4;
        conv_w_kernel<<<(n4 + 255) / 256, 256>>>((const float4*)w, (__half2*)wh, n4);
    }

    static bool attr_set = false;
    if (!attr_set) {
        cudaFuncSetAttribute(bingemm_kernel, cudaFuncAttributeMaxDynamicSharedMemorySize,
                             SMEM_TOTAL);
        attr_set = true;
    }
    dim3 grid(OUT_DIM_ / BN, TOKENS_ / BM);  // (16, 64)
    bingemm_kernel<<<grid, 256, SMEM_TOTAL>>>(xh, wh, bias, out);
}